// round 5
// baseline (speedup 1.0000x reference)
#include <cuda_runtime.h>
#include <cstdint>

#define TV     16384   // T*V
#define VOCABN 1024
#define CTXN   16
#define BATCHN 256
#define ROWS   8       // rows of W per CTA (=> 32B-aligned float4 x2 output stores)

// Each CTA: stages ROWS consecutive rows of W (64KB each) through shared memory
// with fully-coalesced float4 loads; each of the 256 threads owns one batch b,
// performs the 16 data-dependent gathers from smem, accumulates into registers,
// and finally writes a 32B-aligned sector of the output.
__global__ __launch_bounds__(BATCHN, 3)
void lrm_gather_kernel(const void* __restrict__ x_raw,
                       const float* __restrict__ W,
                       const float* __restrict__ bias,
                       float* __restrict__ out)
{
    extern __shared__ float srow[];          // TV floats = 64KB
    const int b = threadIdx.x;               // one thread per batch row

    // ---- detect int32 vs int64 index buffer (JAX x64 ambiguity) ----
    // int64 values are in [0,1024) -> every odd 32-bit word is 0.
    const unsigned* xw = (const unsigned*)x_raw;
    unsigned ored = 0;
#pragma unroll
    for (int i = 0; i < 16; i++) ored |= xw[2 * i + 1];
    const bool is64 = (ored == 0u);

    // ---- load this thread's 16 gather indices into registers ----
    int idx[CTXN];
    if (is64) {
        const long long* x64 = (const long long*)x_raw;
#pragma unroll
        for (int t = 0; t < CTXN; t++)
            idx[t] = (int)x64[b * CTXN + t] + t * VOCABN;
    } else {
        const int* x32 = (const int*)x_raw;
#pragma unroll
        for (int t = 0; t < CTXN; t++)
            idx[t] = x32[b * CTXN + t] + t * VOCABN;
    }

    const int j0 = blockIdx.x * ROWS;
    float acc[ROWS];

    float4* s4 = (float4*)srow;
#pragma unroll 1
    for (int r = 0; r < ROWS; r++) {
        const int j = j0 + r;
        // ---- coalesced stage of row j (16384 floats) into smem ----
        const float4* w4 = (const float4*)(W + (size_t)j * TV);
#pragma unroll
        for (int k = 0; k < TV / 4 / BATCHN; k++)   // 16 iterations
            s4[b + BATCHN * k] = w4[b + BATCHN * k];
        __syncthreads();

        // ---- 16-way gather + bias ----
        float s = bias[j];
#pragma unroll
        for (int t = 0; t < CTXN; t++) s += srow[idx[t]];
        acc[r] = s;
        __syncthreads();   // protect smem before next row overwrites it
    }

    // ---- relu + one 32B-aligned sector store per batch ----
    float* op = out + (size_t)b * TV + j0;
    float4 o0 = make_float4(fmaxf(acc[0], 0.f), fmaxf(acc[1], 0.f),
                            fmaxf(acc[2], 0.f), fmaxf(acc[3], 0.f));
    float4 o1 = make_float4(fmaxf(acc[4], 0.f), fmaxf(acc[5], 0.f),
                            fmaxf(acc[6], 0.f), fmaxf(acc[7], 0.f));
    ((float4*)op)[0] = o0;
    ((float4*)op)[1] = o1;
}

extern "C" void kernel_launch(void* const* d_in, const int* in_sizes, int n_in,
                              void* d_out, int out_size)
{
    const void*  x    = d_in[0];                  // [256,16] int32 or int64 (detected)
    const float* W    = (const float*)d_in[1];    // [16384,16384] fp32
    const float* bias = (const float*)d_in[2];    // [16384] fp32
    float* out = (float*)d_out;                   // [256,16,1024] fp32

    // cudaFuncSetAttribute is not stream-ordered; safe (and idempotent) to
    // call on every launch, including under graph capture.
    cudaFuncSetAttribute(lrm_gather_kernel,
                         cudaFuncAttributeMaxDynamicSharedMemorySize, TV * 4);
    (void)in_sizes; (void)n_in; (void)out_size;

    lrm_gather_kernel<<<TV / ROWS, BATCHN, TV * 4>>>(x, W, bias, out);
}

// round 17
// speedup vs baseline: 1.1305x; 1.1305x over previous
#include <cuda_runtime.h>
#include <cstdint>

#define TV     16384   // T*V
#define VOCABN 1024
#define CTXN   16
#define BATCHN 256
#define ROWS   8       // rows of W per CTA
#define HALF   8192    // floats per half-row (32KB)
#define NSTEPS (2 * ROWS)

__device__ __forceinline__ void cp_async16(uint32_t smem_dst, const void* gmem_src) {
    asm volatile("cp.async.cg.shared.global [%0], [%1], 16;\n"
                 :: "r"(smem_dst), "l"(gmem_src));
}

// Double-buffered cp.async pipeline: while gathering 8 terms from the current
// 32KB half-row in smem, the next 32KB half-row is already in flight. Each CTA
// keeps >=32KB of DRAM traffic outstanding across its barrier/gather windows.
__global__ __launch_bounds__(BATCHN, 3)
void lrm_gather_kernel(const void* __restrict__ x_raw,
                       const float* __restrict__ W,
                       const float* __restrict__ bias,
                       float* __restrict__ out)
{
    extern __shared__ float srow[];          // 2 * HALF floats = 64KB
    const int b = threadIdx.x;               // one thread per batch row

    // ---- detect int32 vs int64 index buffer (JAX x64 ambiguity) ----
    const unsigned* xw = (const unsigned*)x_raw;
    unsigned ored = 0;
#pragma unroll
    for (int i = 0; i < 16; i++) ored |= xw[2 * i + 1];
    const bool is64 = (ored == 0u);

    // ---- 16 gather indices; idx[t] in [t*1024, (t+1)*1024) ----
    int idx[CTXN];
    if (is64) {
        const long long* x64 = (const long long*)x_raw;
#pragma unroll
        for (int t = 0; t < CTXN; t++)
            idx[t] = (int)x64[b * CTXN + t] + t * VOCABN;
    } else {
        const int* x32 = (const int*)x_raw;
#pragma unroll
        for (int t = 0; t < CTXN; t++)
            idx[t] = x32[b * CTXN + t] + t * VOCABN;
    }

    const int j0 = blockIdx.x * ROWS;
    float acc[ROWS];
#pragma unroll
    for (int r = 0; r < ROWS; r++) acc[r] = __ldg(bias + j0 + r);

    const uint32_t sbase = (uint32_t)__cvta_generic_to_shared(srow);

    // prefetch for step s: row r = s>>1, half h = s&1, into buffer (s&1)
    auto prefetch = [&](int s) {
        const int r = s >> 1, h = s & 1;
        const float4* src = (const float4*)(W + (size_t)(j0 + r) * TV + h * HALF);
        const uint32_t dst = sbase + (uint32_t)((s & 1) * HALF) * 4u;
#pragma unroll
        for (int k = 0; k < HALF / 4 / BATCHN; k++)   // 8 x 16B per thread
            cp_async16(dst + (uint32_t)(b + BATCHN * k) * 16u, src + b + BATCHN * k);
        asm volatile("cp.async.commit_group;\n");
    };

    prefetch(0);

#pragma unroll
    for (int s = 0; s < NSTEPS; s++) {
        if (s + 1 < NSTEPS) {
            __syncthreads();                 // gathers on buf[(s+1)&1] (from step s-1) done
            prefetch(s + 1);
            asm volatile("cp.async.wait_group 1;\n");   // buf[s&1] arrived
        } else {
            asm volatile("cp.async.wait_group 0;\n");
        }
        __syncthreads();

        const int h = s & 1;                 // compile-time (loop fully unrolled)
        const float* bp = srow + h * HALF;
        float a = 0.f;
#pragma unroll
        for (int tt = 0; tt < 8; tt++)
            a += bp[idx[h * 8 + tt] - h * HALF];
        acc[s >> 1] += a;
    }

    // ---- relu + one 32B-aligned sector store per batch ----
    float* op = out + (size_t)b * TV + j0;
    float4 o0 = make_float4(fmaxf(acc[0], 0.f), fmaxf(acc[1], 0.f),
                            fmaxf(acc[2], 0.f), fmaxf(acc[3], 0.f));
    float4 o1 = make_float4(fmaxf(acc[4], 0.f), fmaxf(acc[5], 0.f),
                            fmaxf(acc[6], 0.f), fmaxf(acc[7], 0.f));
    ((float4*)op)[0] = o0;
    ((float4*)op)[1] = o1;
}

extern "C" void kernel_launch(void* const* d_in, const int* in_sizes, int n_in,
                              void* d_out, int out_size)
{
    const void*  x    = d_in[0];                  // [256,16] int32 or int64 (detected)
    const float* W    = (const float*)d_in[1];    // [16384,16384] fp32
    const float* bias = (const float*)d_in[2];    // [16384] fp32
    float* out = (float*)d_out;                   // [256,16,1024] fp32

    cudaFuncSetAttribute(lrm_gather_kernel,
                         cudaFuncAttributeMaxDynamicSharedMemorySize, 2 * HALF * 4);
    (void)in_sizes; (void)n_in; (void)out_size;

    lrm_gather_kernel<<<TV / ROWS, BATCHN, 2 * HALF * 4>>>(x, W, bias, out);
}